// round 9
// baseline (speedup 1.0000x reference)
#include <cuda_runtime.h>
#include <cuda_bf16.h>
#include <cstdint>

#define NB 256

// ======================= device scratch =======================
__device__ unsigned char g_m1[NB * 64 * 64];
__device__ unsigned char g_m2[NB * 32 * 32];
__device__ unsigned char g_m3[NB * 32 * 32];
__device__ unsigned char g_m4[NB * 16 * 16];
__device__ float g_p1[NB * 32 * 32 * 32];   // [b][32ic][32][32]
__device__ float g_p2[NB * 64 * 16 * 16];   // [b][64oc][16][16]
__device__ float g_fc1p[64 * NB * 128];     // split-K partials

// ======================= masks (proven) =======================
__global__ void masks_kernel(const int* __restrict__ c_map) {
    int b = blockIdx.x, t = threadIdx.x;
    __shared__ unsigned char cs[64 * 64];
    __shared__ unsigned char m1s[64 * 64];
    __shared__ unsigned char m2s[32 * 32];
    __shared__ unsigned char m3s[32 * 32];

    for (int i = t; i < 4096; i += 256) cs[i] = (unsigned char)c_map[b * 4096 + i];
    __syncthreads();
    for (int i = t; i < 4096; i += 256) {
        int r = i >> 6, c = i & 63, s = 0;
        #pragma unroll
        for (int dr = 0; dr < 3; ++dr) {
            int rr = r + dr;
            if (rr < 64)
                #pragma unroll
                for (int dc = 0; dc < 3; ++dc) {
                    int cc = c + dc;
                    if (cc < 64) s += cs[rr * 64 + cc];
                }
        }
        m1s[i] = (s > 1);
    }
    __syncthreads();
    for (int i = t; i < 4096; i += 256) g_m1[b * 4096 + i] = m1s[i];
    for (int i = t; i < 1024; i += 256) {
        int r = i >> 5, c = i & 31;
        int s = m1s[(2*r)*64 + 2*c] + m1s[(2*r)*64 + 2*c + 1]
              + m1s[(2*r+1)*64 + 2*c] + m1s[(2*r+1)*64 + 2*c + 1];
        m2s[i] = (s > 1);
    }
    __syncthreads();
    for (int i = t; i < 1024; i += 256) g_m2[b * 1024 + i] = m2s[i];
    for (int i = t; i < 1024; i += 256) {
        int r = i >> 5, c = i & 31, s = 0;
        #pragma unroll
        for (int dr = 0; dr < 3; ++dr) {
            int rr = r + dr;
            if (rr < 32)
                #pragma unroll
                for (int dc = 0; dc < 3; ++dc) {
                    int cc = c + dc;
                    if (cc < 32) s += m2s[rr * 32 + cc];
                }
        }
        m3s[i] = (s > 1);
    }
    __syncthreads();
    for (int i = t; i < 1024; i += 256) g_m3[b * 1024 + i] = m3s[i];
    for (int i = t; i < 256; i += 256) {
        int r = i >> 4, c = i & 15;
        int s = m3s[(2*r)*32 + 2*c] + m3s[(2*r)*32 + 2*c + 1]
              + m3s[(2*r+1)*32 + 2*c] + m3s[(2*r+1)*32 + 2*c + 1];
        g_m4[b * 256 + i] = (s > 1);
    }
}

// ======================= conv1 scalar (proven) =======================
__global__ __launch_bounds__(256) void conv1_kernel(const float* __restrict__ x,
                                                    const float* __restrict__ W1,
                                                    const float* __restrict__ b1) {
    __shared__ __align__(16) float xt[66 * 68];
    __shared__ float w1s[32 * 9];
    __shared__ float b1s[32];
    __shared__ unsigned char m1s[64 * 64];
    __shared__ unsigned char m2s[32 * 32];

    int b = blockIdx.x, t = threadIdx.x;
    for (int i = t; i < 66 * 68; i += 256) xt[i] = 0.f;
    __syncthreads();
    for (int i = t; i < 4096; i += 256) {
        int r = i >> 6, c = i & 63;
        xt[(r + 1) * 68 + (c + 1)] = x[b * 4096 + i];
    }
    for (int i = t; i < 288; i += 256) w1s[i] = W1[i];
    if (t < 32) b1s[t] = b1[t];
    for (int i = t; i < 4096; i += 256) m1s[i] = g_m1[b * 4096 + i];
    for (int i = t; i < 1024; i += 256) m2s[i] = g_m2[b * 1024 + i];
    __syncthreads();

    for (int k = 0; k < 4; ++k) {
        int pp = t + 256 * k;
        int pi = pp >> 5, pj = pp & 31;
        float p[4][4];
        #pragma unroll
        for (int rr = 0; rr < 4; ++rr) {
            const float* tp = &xt[(2 * pi + rr) * 68 + 2 * pj];
            float2 a = *(const float2*)tp;
            float2 c = *(const float2*)(tp + 2);
            p[rr][0] = a.x; p[rr][1] = a.y; p[rr][2] = c.x; p[rr][3] = c.y;
        }
        unsigned char ma = m1s[(2*pi)*64 + 2*pj],     mb = m1s[(2*pi)*64 + 2*pj + 1];
        unsigned char mc = m1s[(2*pi+1)*64 + 2*pj],   md = m1s[(2*pi+1)*64 + 2*pj + 1];
        bool mm2 = m2s[pi * 32 + pj] != 0;

        for (int oc = 0; oc < 32; ++oc) {
            const float* w = &w1s[oc * 9];
            float bb = b1s[oc];
            float s[4];
            #pragma unroll
            for (int dr = 0; dr < 2; ++dr)
                #pragma unroll
                for (int dc = 0; dc < 2; ++dc) {
                    s[dr * 2 + dc] =
                          p[dr][dc]   * w[0] + p[dr][dc+1]   * w[1] + p[dr][dc+2]   * w[2]
                        + p[dr+1][dc] * w[3] + p[dr+1][dc+1] * w[4] + p[dr+1][dc+2] * w[5]
                        + p[dr+2][dc] * w[6] + p[dr+2][dc+1] * w[7] + p[dr+2][dc+2] * w[8]
                        + bb;
                }
            float v = 0.f;
            if (mm2) {
                if (ma) v = fmaxf(v, s[0]);
                if (mb) v = fmaxf(v, s[1]);
                if (mc) v = fmaxf(v, s[2]);
                if (md) v = fmaxf(v, s[3]);
            }
            g_p1[((b * 32 + oc) * 32 + pi) * 32 + pj] = v;
        }
    }
}

// ======================= conv2 via mma.sync bf16 (split hi/lo) ===============
// CTA = 1 image, 256 threads = 8 warps (warp w owns M rows w*16..w*16+15).
// 8 tiles: D[128 pos x 64 oc], K = 32ic*9 = 288 (18 k16-steps, 3 chunks of 96).
// D = Ahi*Bhi + Alo*Bhi + Ahi*Blo (fp32 accumulate in registers).
#define KP 296                               // B k-stride (words stride 148 ≡ 20 mod 32)
#define AP 104                               // A k-stride (words stride 52 ≡ 20 mod 32)
#define OF_BHI 0                             // 64*KP*2      = 37888
#define OF_BLO 37888                         // 37888        -> 75776
#define OF_AHI 75776                         // 128*AP*2     = 26624 -> 102400
#define OF_ALO 102400                        // 26624        -> 129024
#define OF_SLX 129024                        // union: slice 32*6*34*4=26112 / pex 128*65*4=33280
#define OF_BIAS 162304                       // 64 f32
#define OF_M3  162560                        // 1024
#define OF_M4  163584                        // 256
#define C2M_SIZE 163840

__device__ __forceinline__ void mma_bf16_16816(float* d, const uint32_t* a,
                                               uint32_t b0, uint32_t b1) {
    asm volatile(
        "mma.sync.aligned.m16n8k16.row.col.f32.bf16.bf16.f32 "
        "{%0,%1,%2,%3}, {%4,%5,%6,%7}, {%8,%9}, {%0,%1,%2,%3};\n"
        : "+f"(d[0]), "+f"(d[1]), "+f"(d[2]), "+f"(d[3])
        : "r"(a[0]), "r"(a[1]), "r"(a[2]), "r"(a[3]), "r"(b0), "r"(b1));
}
__device__ __forceinline__ void bf16_split(float v, unsigned short& h, unsigned short& l) {
    __nv_bfloat16 hb = __float2bfloat16(v);
    float hf = __bfloat162float(hb);
    __nv_bfloat16 lb = __float2bfloat16(v - hf);
    h = __bfloat16_as_ushort(hb);
    l = __bfloat16_as_ushort(lb);
}

__global__ __launch_bounds__(256, 1) void conv2m_kernel(const float* __restrict__ W2,
                                                        const float* __restrict__ b2) {
    extern __shared__ __align__(16) char sm[];
    unsigned short* bhi = (unsigned short*)(sm + OF_BHI);
    unsigned short* blo = (unsigned short*)(sm + OF_BLO);
    unsigned short* ahi = (unsigned short*)(sm + OF_AHI);
    unsigned short* alo = (unsigned short*)(sm + OF_ALO);
    float* slice = (float*)(sm + OF_SLX);
    float* pex   = (float*)(sm + OF_SLX);
    float* bias  = (float*)(sm + OF_BIAS);
    unsigned char* m3s = (unsigned char*)(sm + OF_M3);
    unsigned char* m4s = (unsigned char*)(sm + OF_M4);

    int b = blockIdx.x, t = threadIdx.x;
    int w = t >> 5, lane = t & 31;
    int lr = lane >> 2, lc = lane & 3;       // fragment row group / k|n group

    // ---- B (weights) hi/lo, layout [n][k] (col-major KxN) ----
    for (int e = t; e < 64 * 288; e += 256) {
        int n = e / 288, k = e % 288, ic = k / 9, j = k % 9;
        unsigned short h, l;
        bf16_split(W2[(n * 32 + ic) * 9 + j], h, l);
        bhi[n * KP + k] = h;
        blo[n * KP + k] = l;
    }
    if (t < 64) bias[t] = b2[t];
    for (int i = t; i < 1024; i += 256) m3s[i] = g_m3[b * 1024 + i];
    for (int i = t; i < 256; i += 256) m4s[i] = g_m4[b * 256 + i];
    __syncthreads();

    for (int tile = 0; tile < 8; ++tile) {
        int r0 = tile * 4;

        // ---- p1 slice [32ic][6 rows r0-1..r0+4][34 cols padded] ----
        for (int i = t; i < 6528; i += 256) slice[i] = 0.f;
        __syncthreads();
        for (int e = t; e < 6144; e += 256) {
            int ic = e / 192, rr = (e / 32) % 6, cc = e & 31;
            int gr = r0 - 1 + rr;
            if (gr >= 0 && gr < 32)
                slice[ic * 204 + rr * 34 + 1 + cc] =
                    g_p1[((b * 32 + ic) * 32 + gr) * 32 + cc];
        }
        __syncthreads();

        float acc[8][4];
        #pragma unroll
        for (int nt = 0; nt < 8; ++nt)
            acc[nt][0] = acc[nt][1] = acc[nt][2] = acc[nt][3] = 0.f;

        for (int chunk = 0; chunk < 3; ++chunk) {
            int kg0 = chunk * 96;
            // ---- build A hi/lo chunk [128 rows][96 k] from fp32 slice ----
            {
                int row = t >> 1, half = t & 1;
                int rl = row >> 5, cc = row & 31;
                int kk = kg0 + half * 48;
                int ic = kk / 9, j = kk % 9;
                const float* sbase = &slice[rl * 34 + cc];
                #pragma unroll 4
                for (int q = 0; q < 48; ++q) {
                    float v = sbase[ic * 204 + (j / 3) * 34 + (j % 3)];
                    unsigned short h, l;
                    bf16_split(v, h, l);
                    int kl = half * 48 + q;
                    ahi[row * AP + kl] = h;
                    alo[row * AP + kl] = l;
                    if (++j == 9) { j = 0; ++ic; }
                }
            }
            __syncthreads();

            // ---- 6 k16-steps of mma ----
            for (int ks = 0; ks < 6; ++ks) {
                int kk = ks * 16;
                int abase = (w * 16 + lr) * AP + kk + lc * 2;
                uint32_t aH[4], aL[4];
                aH[0] = *(const uint32_t*)&ahi[abase];
                aH[1] = *(const uint32_t*)&ahi[abase + 8 * AP];
                aH[2] = *(const uint32_t*)&ahi[abase + 8];
                aH[3] = *(const uint32_t*)&ahi[abase + 8 * AP + 8];
                aL[0] = *(const uint32_t*)&alo[abase];
                aL[1] = *(const uint32_t*)&alo[abase + 8 * AP];
                aL[2] = *(const uint32_t*)&alo[abase + 8];
                aL[3] = *(const uint32_t*)&alo[abase + 8 * AP + 8];
                int kgl = kg0 + kk + lc * 2;
                #pragma unroll
                for (int nt = 0; nt < 8; ++nt) {
                    int bbase = (nt * 8 + lr) * KP + kgl;
                    uint32_t bH0 = *(const uint32_t*)&bhi[bbase];
                    uint32_t bH1 = *(const uint32_t*)&bhi[bbase + 8];
                    uint32_t bL0 = *(const uint32_t*)&blo[bbase];
                    uint32_t bL1 = *(const uint32_t*)&blo[bbase + 8];
                    mma_bf16_16816(acc[nt], aH, bH0, bH1);
                    mma_bf16_16816(acc[nt], aL, bH0, bH1);
                    mma_bf16_16816(acc[nt], aH, bL0, bL1);
                }
            }
            __syncthreads();   // before next chunk overwrites A
        }

        // ---- epilogue: bias + m3-gated relu into pex ----
        {
            int rlo = w * 16 + lr, rhi = rlo + 8;
            bool m3lo = m3s[(r0 + (rlo >> 5)) * 32 + (rlo & 31)] != 0;
            bool m3hi = m3s[(r0 + (rhi >> 5)) * 32 + (rhi & 31)] != 0;
            #pragma unroll
            for (int nt = 0; nt < 8; ++nt) {
                int n0 = nt * 8 + lc * 2;
                float y0 = acc[nt][0] + bias[n0];
                float y1 = acc[nt][1] + bias[n0 + 1];
                float y2 = acc[nt][2] + bias[n0];
                float y3 = acc[nt][3] + bias[n0 + 1];
                pex[rlo * 65 + n0]     = (m3lo && y0 > 0.f) ? y0 : 0.f;
                pex[rlo * 65 + n0 + 1] = (m3lo && y1 > 0.f) ? y1 : 0.f;
                pex[rhi * 65 + n0]     = (m3hi && y2 > 0.f) ? y2 : 0.f;
                pex[rhi * 65 + n0 + 1] = (m3hi && y3 > 0.f) ? y3 : 0.f;
            }
        }
        __syncthreads();

        // ---- 2x2 maxpool + m4 gate -> g_p2 ----
        {
            int po = t & 31, ppr = po >> 4, ppc = po & 15, ocg = (t >> 5) * 8;
            int gpr = tile * 2 + ppr;
            bool m4v = m4s[gpr * 16 + ppc] != 0;
            int m00 = (2 * ppr) * 32 + 2 * ppc;
            #pragma unroll
            for (int q = 0; q < 8; ++q) {
                int oc = ocg + q;
                float v = fmaxf(fmaxf(pex[m00 * 65 + oc], pex[(m00 + 1) * 65 + oc]),
                                fmaxf(pex[(m00 + 32) * 65 + oc], pex[(m00 + 33) * 65 + oc]));
                g_p2[((b * 64 + oc) * 16 + gpr) * 16 + ppc] = m4v ? v : 0.f;
            }
        }
        __syncthreads();
    }
}

// ======================= fc1 scalar split-K (measured R6) ====================
__global__ __launch_bounds__(256) void fc1_kernel(const float* __restrict__ Wfc1) {
    __shared__ __align__(16) float Asm[32 * 36];
    __shared__ __align__(16) float Bsm[128 * 32];
    int b0 = blockIdx.x * 32;
    int ks = blockIdx.y;
    int k0 = ks * 256;
    int t = threadIdx.x, lane = t & 31, wid = t >> 5;
    int bi = lane, ng = wid * 16;

    float acc[16];
    #pragma unroll
    for (int q = 0; q < 16; ++q) acc[q] = 0.f;

    for (int kk = 0; kk < 256; kk += 32) {
        for (int r = wid; r < 32; r += 8)
            Asm[r * 36 + lane] = g_p2[(b0 + r) * 16384 + k0 + kk + lane];
        #pragma unroll
        for (int r = 0; r < 16; ++r)
            Bsm[(ng + r) * 32 + lane] = Wfc1[(ng + r) * 16384 + k0 + kk + lane];
        __syncthreads();
        #pragma unroll
        for (int j4 = 0; j4 < 8; ++j4) {
            float4 av = *(const float4*)&Asm[bi * 36 + j4 * 4];
            #pragma unroll
            for (int q = 0; q < 16; ++q) {
                float4 bv = *(const float4*)&Bsm[(ng + q) * 32 + j4 * 4];
                acc[q] += av.x * bv.x + av.y * bv.y + av.z * bv.z + av.w * bv.w;
            }
        }
        __syncthreads();
    }
    #pragma unroll
    for (int q = 0; q < 16; ++q)
        g_fc1p[(ks * NB + b0 + bi) * 128 + ng + q] = acc[q];
}

// ======================= fc2 (reduce + bias + relu + GEMV) ===================
__global__ __launch_bounds__(128) void fc2_kernel(const float* __restrict__ Wfc2,
                                                  const float* __restrict__ bfc2,
                                                  const float* __restrict__ bfc1,
                                                  float* __restrict__ out) {
    int b = blockIdx.x, t = threadIdx.x;
    __shared__ float hs[128];
    float s = 0.f;
    #pragma unroll
    for (int ks = 0; ks < 64; ++ks) s += g_fc1p[(ks * NB + b) * 128 + t];
    s += bfc1[t];
    hs[t] = fmaxf(s, 0.f);
    __syncthreads();
    int wid = t >> 5, lane = t & 31;
    for (int o = wid; o < 10; o += 4) {
        float p = 0.f;
        #pragma unroll
        for (int q = 0; q < 4; ++q)
            p += hs[lane + q * 32] * Wfc2[o * 128 + lane + q * 32];
        #pragma unroll
        for (int off = 16; off; off >>= 1)
            p += __shfl_xor_sync(0xffffffffu, p, off);
        if (lane == 0) out[b * 10 + o] = p + bfc2[o];
    }
}

// ======================= launch =======================
extern "C" void kernel_launch(void* const* d_in, const int* in_sizes, int n_in,
                              void* d_out, int out_size) {
    (void)in_sizes; (void)n_in; (void)out_size;
    const float* x     = (const float*)d_in[0];
    const int*   c_map = (const int*)d_in[1];
    const float* W1    = (const float*)d_in[2];
    const float* b1    = (const float*)d_in[3];
    const float* W2    = (const float*)d_in[4];
    const float* b2    = (const float*)d_in[5];
    const float* Wfc1  = (const float*)d_in[6];
    const float* bfc1  = (const float*)d_in[7];
    const float* Wfc2  = (const float*)d_in[8];
    const float* bfc2  = (const float*)d_in[9];
    float* out = (float*)d_out;

    masks_kernel<<<NB, 256>>>(c_map);
    conv1_kernel<<<NB, 256>>>(x, W1, b1);
    cudaFuncSetAttribute(conv2m_kernel, cudaFuncAttributeMaxDynamicSharedMemorySize, C2M_SIZE);
    conv2m_kernel<<<NB, 256, C2M_SIZE>>>(W2, b2);
    fc1_kernel<<<dim3(8, 64), 256>>>(Wfc1);
    fc2_kernel<<<NB, 128>>>(Wfc2, bfc2, bfc1, out);
}